// round 1
// baseline (speedup 1.0000x reference)
#include <cuda_runtime.h>
#include <cstddef>

#define H      128
#define EMB    64
#define LAYERS 3
#define N_MAX  100000
#define E_MAX  1600000
#define G_MAX  1024

// ---------------- scratch (device globals; no allocation allowed) ----------------
__device__ float g_P [(size_t)N_MAX * H];   // pre-BN activations (GEMM input w/ fused BN-relu)
__device__ float g_HW[(size_t)N_MAX * H];   // GEMM output h @ Ws[l]
__device__ int   g_deg[N_MAX];
__device__ float g_dinv[N_MAX];
__device__ int   g_rowptr[N_MAX + 1];
__device__ int   g_cursor[N_MAX];
__device__ int   g_csrsrc[E_MAX];
__device__ float g_csrw[E_MAX];
__device__ int   g_chunksum[128];
__device__ int   g_chunkoff[128];
__device__ float g_bnsum[LAYERS * H];
__device__ float g_bnsq [LAYERS * H];
__device__ float g_ts[(LAYERS + 1) * H];    // per-slot BN scale (slot 0 = identity)
__device__ float g_tt[(LAYERS + 1) * H];    // per-slot BN shift
__device__ int   g_gstart[G_MAX + 1];
__device__ float g_pooled[(size_t)G_MAX * H];

// ---------------- init ----------------
__global__ void k_init(int Nn) {
    int i = blockIdx.x * blockDim.x + threadIdx.x;
    if (i < Nn) { g_deg[i] = 0; g_cursor[i] = 0; }
    if (i < H)  { g_ts[i] = 1.0f; g_tt[i] = 0.0f; }
    if (i < LAYERS * H) { g_bnsum[i] = 0.0f; g_bnsq[i] = 0.0f; }
}

// ---------------- degree count / dinv ----------------
__global__ void k_count(const int* __restrict__ ei, int E) {
    int e = blockIdx.x * blockDim.x + threadIdx.x;
    if (e < E) atomicAdd(&g_deg[ei[E + e]], 1);
}

__global__ void k_dinv(int Nn) {
    int i = blockIdx.x * blockDim.x + threadIdx.x;
    if (i < Nn) g_dinv[i] = rsqrtf((float)g_deg[i] + 1.0f);
}

// ---------------- exclusive scan (1024-elem chunks) ----------------
__global__ void k_chunksum(int Nn) {
    __shared__ int sm[256];
    int base = blockIdx.x * 1024;
    int s = 0;
    for (int j = threadIdx.x; j < 1024; j += 256) {
        int i = base + j;
        if (i < Nn) s += g_deg[i];
    }
    sm[threadIdx.x] = s; __syncthreads();
    for (int d = 128; d > 0; d >>= 1) {
        if (threadIdx.x < d) sm[threadIdx.x] += sm[threadIdx.x + d];
        __syncthreads();
    }
    if (threadIdx.x == 0) g_chunksum[blockIdx.x] = sm[0];
}

__global__ void k_scanchunks(int nb) {
    if (threadIdx.x == 0) {
        int acc = 0;
        for (int b = 0; b < nb; b++) { g_chunkoff[b] = acc; acc += g_chunksum[b]; }
    }
}

__global__ void k_scanlocal(int Nn, int E) {
    __shared__ int sm[1024];
    int i = blockIdx.x * 1024 + threadIdx.x;
    int v = (i < Nn) ? g_deg[i] : 0;
    sm[threadIdx.x] = v; __syncthreads();
    for (int d = 1; d < 1024; d <<= 1) {
        int x = (threadIdx.x >= d) ? sm[threadIdx.x - d] : 0;
        __syncthreads();
        sm[threadIdx.x] += x;
        __syncthreads();
    }
    if (i < Nn) g_rowptr[i] = g_chunkoff[blockIdx.x] + sm[threadIdx.x] - v;  // exclusive
    if (i == 0) g_rowptr[Nn] = E;
}

// ---------------- CSR scatter ----------------
__global__ void k_scatter(const int* __restrict__ ei, int E) {
    int e = blockIdx.x * blockDim.x + threadIdx.x;
    if (e >= E) return;
    int s = ei[e], d = ei[E + e];
    int pos = g_rowptr[d] + atomicAdd(&g_cursor[d], 1);
    g_csrsrc[pos] = s;
    g_csrw[pos]   = g_dinv[s] * g_dinv[d];
}

// ---------------- graph boundary (batch is sorted) ----------------
__global__ void k_gstart(const int* __restrict__ batch, int Nn, int G) {
    int g = blockIdx.x * blockDim.x + threadIdx.x;
    if (g > G) return;
    if (g == G) { g_gstart[G] = Nn; return; }
    int lo = 0, hi = Nn;
    while (lo < hi) {
        int mid = (lo + hi) >> 1;
        if (batch[mid] < g) lo = mid + 1; else hi = mid;
    }
    g_gstart[g] = lo;
}

// ---------------- SGEMM: C[M,128] = f(A)[M,128] @ B[128,128] (+bias) ----------------
// TRANSFORM=1: A element at channel k becomes relu(a*s[k]+t[k])  (fused BN+ReLU)
template <int TRANSFORM>
__global__ void __launch_bounds__(256) k_gemm(
    const float* __restrict__ A, const float* __restrict__ B, float* __restrict__ C,
    int M, const float* __restrict__ s, const float* __restrict__ t,
    const float* __restrict__ bias)
{
    __shared__ float As[16][132];   // [k][m], padded
    __shared__ float Bs[16][128];   // [k][n]
    const int tid = threadIdx.x;
    const int tx = tid & 15, ty = tid >> 4;
    const int m0 = blockIdx.x * 128;

    float acc[8][8];
#pragma unroll
    for (int i = 0; i < 8; i++)
#pragma unroll
        for (int j = 0; j < 8; j++) acc[i][j] = 0.0f;

    for (int kt = 0; kt < H; kt += 16) {
#pragma unroll
        for (int l = 0; l < 2; l++) {
            int idx = tid + l * 256;
            int row = idx >> 2, c4 = (idx & 3) * 4;
            int gm = m0 + row;
            float4 v = make_float4(0.f, 0.f, 0.f, 0.f);
            if (gm < M) v = *(const float4*)(A + (size_t)gm * H + kt + c4);
            if (TRANSFORM) {
                int kg = kt + c4;
                v.x = fmaxf(fmaf(v.x, s[kg],     t[kg]),     0.f);
                v.y = fmaxf(fmaf(v.y, s[kg + 1], t[kg + 1]), 0.f);
                v.z = fmaxf(fmaf(v.z, s[kg + 2], t[kg + 2]), 0.f);
                v.w = fmaxf(fmaf(v.w, s[kg + 3], t[kg + 3]), 0.f);
            }
            As[c4 + 0][row] = v.x; As[c4 + 1][row] = v.y;
            As[c4 + 2][row] = v.z; As[c4 + 3][row] = v.w;
        }
#pragma unroll
        for (int l = 0; l < 2; l++) {
            int idx = tid + l * 256;
            int row = idx >> 5, cc = (idx & 31) * 4;
            *(float4*)(&Bs[row][cc]) = *(const float4*)(B + (size_t)(kt + row) * H + cc);
        }
        __syncthreads();
#pragma unroll
        for (int k = 0; k < 16; k++) {
            float a[8], b[8];
            *(float4*)(a)     = *(const float4*)(&As[k][ty * 8]);
            *(float4*)(a + 4) = *(const float4*)(&As[k][ty * 8 + 4]);
            *(float4*)(b)     = *(const float4*)(&Bs[k][tx * 8]);
            *(float4*)(b + 4) = *(const float4*)(&Bs[k][tx * 8 + 4]);
#pragma unroll
            for (int i = 0; i < 8; i++)
#pragma unroll
                for (int j = 0; j < 8; j++)
                    acc[i][j] = fmaf(a[i], b[j], acc[i][j]);
        }
        __syncthreads();
    }

#pragma unroll
    for (int i = 0; i < 8; i++) {
        int gm = m0 + ty * 8 + i;
        if (gm < M) {
#pragma unroll
            for (int j = 0; j < 8; j += 4) {
                int n = tx * 8 + j;
                float4 v = make_float4(acc[i][j], acc[i][j + 1], acc[i][j + 2], acc[i][j + 3]);
                if (bias) { v.x += bias[n]; v.y += bias[n + 1]; v.z += bias[n + 2]; v.w += bias[n + 3]; }
                *(float4*)(C + (size_t)gm * H + n) = v;
            }
        }
    }
}

// ---------------- edge aggregation: warp per dst node (no atomics) ----------------
__global__ void k_agg(const float* __restrict__ HWp, const float* __restrict__ bias,
                      float* __restrict__ OUT, int Nn)
{
    int w    = (blockIdx.x * blockDim.x + threadIdx.x) >> 5;
    int lane = threadIdx.x & 31;
    if (w >= Nn) return;
    const float4* hw4 = (const float4*)HWp;
    int e0 = g_rowptr[w], e1 = g_rowptr[w + 1];
    float4 acc = make_float4(0.f, 0.f, 0.f, 0.f);
    for (int e = e0; e < e1; e++) {
        int   src = g_csrsrc[e];
        float wt  = g_csrw[e];
        float4 v = hw4[(size_t)src * 32 + lane];
        acc.x = fmaf(wt, v.x, acc.x);
        acc.y = fmaf(wt, v.y, acc.y);
        acc.z = fmaf(wt, v.z, acc.z);
        acc.w = fmaf(wt, v.w, acc.w);
    }
    float di = g_dinv[w];
    float sn = di * di;                       // 1/deg (self-loop norm)
    float4 sv = hw4[(size_t)w * 32 + lane];
    acc.x = fmaf(sn, sv.x, acc.x) + bias[lane * 4 + 0];
    acc.y = fmaf(sn, sv.y, acc.y) + bias[lane * 4 + 1];
    acc.z = fmaf(sn, sv.z, acc.z) + bias[lane * 4 + 2];
    acc.w = fmaf(sn, sv.w, acc.w) + bias[lane * 4 + 3];
    ((float4*)OUT)[(size_t)w * 32 + lane] = acc;
}

// ---------------- BatchNorm statistics & finalize ----------------
__global__ void k_bnstats(const float* __restrict__ P, int Nn, int layer) {
    int c = threadIdx.x;  // 128 threads
    float s = 0.f, q = 0.f;
    for (int r = blockIdx.x; r < Nn; r += gridDim.x) {
        float v = P[(size_t)r * H + c];
        s += v;
        q = fmaf(v, v, q);
    }
    atomicAdd(&g_bnsum[layer * H + c], s);
    atomicAdd(&g_bnsq [layer * H + c], q);
}

__global__ void k_bnfin(const float* __restrict__ gammas, const float* __restrict__ betas,
                        int Nn, int layer) {
    int c = threadIdx.x;
    float invN = 1.0f / (float)Nn;
    float mean = g_bnsum[layer * H + c] * invN;
    float var  = g_bnsq [layer * H + c] * invN - mean * mean;
    float inv  = rsqrtf(var + 1e-5f);
    float sc   = gammas[layer * H + c] * inv;
    g_ts[(layer + 1) * H + c] = sc;
    g_tt[(layer + 1) * H + c] = betas[layer * H + c] - mean * sc;
}

// ---------------- global mean pool (block per graph; applies layer-3 BN+ReLU) ----------------
__global__ void k_pool(const float* __restrict__ P) {
    int g = blockIdx.x, c = threadIdx.x;
    int a = g_gstart[g], b = g_gstart[g + 1];
    float sc = g_ts[LAYERS * H + c], tt = g_tt[LAYERS * H + c];
    float acc = 0.f;
    for (int r = a; r < b; r++)
        acc += fmaxf(fmaf(P[(size_t)r * H + c], sc, tt), 0.f);
    g_pooled[(size_t)g * H + c] = acc / fmaxf((float)(b - a), 1.0f);
}

// ---------------- head MLP: out = relu(pooled@W1+b1)@W2+b2 ----------------
__global__ void k_mlp(const float* __restrict__ W1, const float* __restrict__ b1,
                      const float* __restrict__ W2, const float* __restrict__ b2,
                      float* __restrict__ out) {
    __shared__ float p[H], t1[H];
    int g = blockIdx.x, c = threadIdx.x;
    p[c] = g_pooled[(size_t)g * H + c];
    __syncthreads();
    float acc = b1[c];
#pragma unroll
    for (int k = 0; k < H; k++) acc = fmaf(p[k], W1[k * H + c], acc);
    t1[c] = fmaxf(acc, 0.f);
    __syncthreads();
    if (c < EMB) {
        float o = b2[c];
#pragma unroll
        for (int k = 0; k < H; k++) o = fmaf(t1[k], W2[k * EMB + c], o);
        out[(size_t)g * EMB + c] = o;
    }
}

// ---------------- launch ----------------
extern "C" void kernel_launch(void* const* d_in, const int* in_sizes, int n_in,
                              void* d_out, int out_size)
{
    const float* x      = (const float*)d_in[0];
    const int*   ei     = (const int*)  d_in[1];
    const int*   batch  = (const int*)  d_in[2];
    const float* W_in   = (const float*)d_in[3];
    const float* b_in   = (const float*)d_in[4];
    const float* Ws     = (const float*)d_in[5];
    const float* bs     = (const float*)d_in[6];
    const float* gammas = (const float*)d_in[7];
    const float* betas  = (const float*)d_in[8];
    const float* W1     = (const float*)d_in[9];
    const float* b1     = (const float*)d_in[10];
    const float* W2     = (const float*)d_in[11];
    const float* b2     = (const float*)d_in[12];

    int Nn = in_sizes[0] / H;
    int E  = in_sizes[1] / 2;
    int G  = out_size / EMB;

    float *P, *HWp, *ts, *tt;
    cudaGetSymbolAddress((void**)&P,   g_P);
    cudaGetSymbolAddress((void**)&HWp, g_HW);
    cudaGetSymbolAddress((void**)&ts,  g_ts);
    cudaGetSymbolAddress((void**)&tt,  g_tt);

    // graph structure (recomputed every launch; deterministic)
    k_init<<<(Nn + 255) / 256, 256>>>(Nn);
    k_count<<<(E + 255) / 256, 256>>>(ei, E);
    k_dinv<<<(Nn + 255) / 256, 256>>>(Nn);
    int nb = (Nn + 1023) / 1024;
    k_chunksum<<<nb, 256>>>(Nn);
    k_scanchunks<<<1, 32>>>(nb);
    k_scanlocal<<<nb, 1024>>>(Nn, E);
    k_scatter<<<(E + 255) / 256, 256>>>(ei, E);
    k_gstart<<<(G + 256) / 256, 256>>>(batch, Nn, G);

    int mblocks = (Nn + 127) / 128;

    // input projection: P = x@W_in + b_in  (ReLU deferred to slot-0 identity transform)
    k_gemm<0><<<mblocks, 256>>>(x, W_in, P, Nn, nullptr, nullptr, b_in);

    for (int l = 0; l < LAYERS; l++) {
        // HW = relu(bn(P)) @ Ws[l]   (BN+ReLU fused into A-tile load; slot0 = identity)
        k_gemm<1><<<mblocks, 256>>>(P, Ws + l * H * H, HWp, Nn, ts + l * H, tt + l * H, nullptr);
        // P = agg(HW) + HW*self_norm + bs[l]   (pre-BN)
        k_agg<<<(Nn * 32 + 255) / 256, 256>>>(HWp, bs + l * H, P, Nn);
        k_bnstats<<<296, 128>>>(P, Nn, l);
        k_bnfin<<<1, 128>>>(gammas, betas, Nn, l);
    }

    k_pool<<<G, 128>>>(P);
    k_mlp<<<G, 128>>>(W1, b1, W2, b2, (float*)d_out);
}